// round 4
// baseline (speedup 1.0000x reference)
#include <cuda_runtime.h>
#include <cuda_bf16.h>
#include <math.h>
#include <stdint.h>

#define N_NODES 65536
#define N_EDGES 1048576
#define IN_FEATS 128
#define N_HIDDEN 64

// ---------------- device scratch (no allocations allowed) ----------------
__device__ float g_h  [N_NODES * N_HIDDEN];
__device__ float g_h2 [N_NODES * N_HIDDEN];
__device__ float g_invA[N_NODES];
__device__ float g_invB[N_NODES];
__device__ int   g_deg[N_NODES];
__device__ int   g_rowptr[N_NODES + 4];
__device__ int   g_cursor[N_NODES];
__device__ int   g_csrc[N_EDGES];

// ---------------- packed f32x2 helpers ----------------
__device__ __forceinline__ uint64_t pack2(float x, float y) {
    uint64_t r; asm("mov.b64 %0, {%1, %2};" : "=l"(r) : "f"(x), "f"(y)); return r;
}
__device__ __forceinline__ uint64_t dup2(float x) {
    uint64_t r; asm("mov.b64 %0, {%1, %1};" : "=l"(r) : "f"(x)); return r;
}
__device__ __forceinline__ void fma2(uint64_t& d, uint64_t a, uint64_t b) {
    asm("fma.rn.f32x2 %0, %1, %2, %0;" : "+l"(d) : "l"(a), "l"(b));
}
__device__ __forceinline__ void unpack2(uint64_t p, float& x, float& y) {
    asm("mov.b64 {%0, %1}, %2;" : "=f"(x), "=f"(y) : "l"(p));
}

// ---------------- GEMM: C[M,64] = act(A[M,K] @ B[K,64] + bias), f32x2 ----------------
template<int K, bool RELU>
__global__ void k_gemm(const float* __restrict__ A, const float* __restrict__ B,
                       const float* __restrict__ bias, float* __restrict__ C,
                       int do_zero) {
    __shared__ float As[32][132];
    __shared__ float Bs[32][64];

    int tid = threadIdx.x;
    if (do_zero) {                  // fold g_deg zeroing into GEMM1
        int z = blockIdx.x * 256 + tid;
        if (z < N_NODES) g_deg[z] = 0;
    }

    int tx = tid & 15;              // 4 cols
    int ty = tid >> 4;              // 8 rows
    long row0 = (long)blockIdx.x * 128;

    uint64_t acc[4][4];
    #pragma unroll
    for (int p = 0; p < 4; p++)
        #pragma unroll
        for (int j = 0; j < 4; j++) acc[p][j] = 0ull;

    for (int k0 = 0; k0 < K; k0 += 32) {
        #pragma unroll
        for (int it = 0; it < 4; it++) {
            int idx = tid + it * 256;
            int r  = idx >> 3;
            int kc = (idx & 7) << 2;
            float4 v = *(const float4*)(A + (row0 + r) * K + k0 + kc);
            As[kc + 0][r] = v.x;
            As[kc + 1][r] = v.y;
            As[kc + 2][r] = v.z;
            As[kc + 3][r] = v.w;
        }
        #pragma unroll
        for (int it = 0; it < 2; it++) {
            int idx = tid + it * 256;
            int kk = idx >> 4;
            int cc = (idx & 15) << 2;
            *(float4*)&Bs[kk][cc] = *(const float4*)(B + (size_t)(k0 + kk) * 64 + cc);
        }
        __syncthreads();

        #pragma unroll
        for (int k = 0; k < 32; k++) {
            float4 a01 = *(const float4*)&As[k][ty * 8];
            float4 a23 = *(const float4*)&As[k][ty * 8 + 4];
            float4 bv  = *(const float4*)&Bs[k][tx * 4];
            uint64_t ap[4];
            ap[0] = pack2(a01.x, a01.y);
            ap[1] = pack2(a01.z, a01.w);
            ap[2] = pack2(a23.x, a23.y);
            ap[3] = pack2(a23.z, a23.w);
            uint64_t bd[4];
            bd[0] = dup2(bv.x); bd[1] = dup2(bv.y);
            bd[2] = dup2(bv.z); bd[3] = dup2(bv.w);
            #pragma unroll
            for (int p = 0; p < 4; p++)
                #pragma unroll
                for (int j = 0; j < 4; j++)
                    fma2(acc[p][j], ap[p], bd[j]);
        }
        __syncthreads();
    }

    float4 bb = *(const float4*)(bias + tx * 4);
    float bbv[4] = {bb.x, bb.y, bb.z, bb.w};
    #pragma unroll
    for (int p = 0; p < 4; p++) {
        long r0 = row0 + ty * 8 + 2 * p;
        float o0[4], o1[4];
        #pragma unroll
        for (int j = 0; j < 4; j++) {
            float lo, hi;
            unpack2(acc[p][j], lo, hi);
            lo += bbv[j]; hi += bbv[j];
            if (RELU) { lo = fmaxf(lo, 0.f); hi = fmaxf(hi, 0.f); }
            o0[j] = lo; o1[j] = hi;
        }
        *(float4*)(C + r0 * 64 + tx * 4)       = make_float4(o0[0], o0[1], o0[2], o0[3]);
        *(float4*)(C + (r0 + 1) * 64 + tx * 4) = make_float4(o1[0], o1[1], o1[2], o1[3]);
    }
}

// ---------------- fused histogram (4 edges/thread) + inv-norm of h ----------------
// 262144 threads: 4 edge atomics each; 4 lanes per node for the norm
__global__ void k_hist_norm(const int* __restrict__ dst, const float* __restrict__ h) {
    int t = blockIdx.x * 256 + threadIdx.x;          // 0..262143
    int4 d4 = ((const int4*)dst)[t];
    atomicAdd(&g_deg[d4.x], 1);
    atomicAdd(&g_deg[d4.y], 1);
    atomicAdd(&g_deg[d4.z], 1);
    atomicAdd(&g_deg[d4.w], 1);

    int n = t >> 2;
    int q = threadIdx.x & 3;
    unsigned qmask = 0xFu << (threadIdx.x & 28);
    const float4* h4 = (const float4*)(h + (size_t)n * N_HIDDEN) + q * 4;
    float qs = 0.f;
    #pragma unroll
    for (int i = 0; i < 4; i++) {
        float4 v = h4[i];
        qs += v.x * v.x + v.y * v.y + v.z * v.z + v.w * v.w;
    }
    qs += __shfl_xor_sync(qmask, qs, 2);
    qs += __shfl_xor_sync(qmask, qs, 1);
    if (q == 0) g_invA[n] = 1.0f / fmaxf(sqrtf(qs), 1e-12f);
}

// ---------------- single-block exclusive scan of g_deg -> rowptr, cursor ----------------
__global__ void k_scan() {
    __shared__ int wsum[32];
    int t = threadIdx.x;            // 1024 threads, 64 elements each
    int base = t * 64;
    const int4* dp = (const int4*)(g_deg + base);

    int sum = 0;
    #pragma unroll
    for (int i = 0; i < 16; i++) { int4 v = dp[i]; sum += v.x + v.y + v.z + v.w; }

    int lane = t & 31, wid = t >> 5;
    int x = sum;
    #pragma unroll
    for (int o = 1; o < 32; o <<= 1) {
        int y = __shfl_up_sync(0xffffffffu, x, o);
        if (lane >= o) x += y;
    }
    if (lane == 31) wsum[wid] = x;
    __syncthreads();
    if (wid == 0) {
        int v = wsum[lane];
        #pragma unroll
        for (int o = 1; o < 32; o <<= 1) {
            int y = __shfl_up_sync(0xffffffffu, v, o);
            if (lane >= o) v += y;
        }
        wsum[lane] = v;
    }
    __syncthreads();
    int run = x - sum + (wid ? wsum[wid - 1] : 0);

    #pragma unroll
    for (int i = 0; i < 16; i++) {
        int4 v = dp[i];
        int4 r;
        r.x = run;
        r.y = r.x + v.x;
        r.z = r.y + v.y;
        r.w = r.z + v.z;
        run = r.w + v.w;
        ((int4*)(g_rowptr + base))[i] = r;
        ((int4*)(g_cursor + base))[i] = r;
    }
    if (t == 1023) g_rowptr[N_NODES] = N_EDGES;
}

// ---------------- scatter, 4 edges/thread (pipelined atomics) ----------------
__global__ void k_scatter(const int* __restrict__ src, const int* __restrict__ dst) {
    int t = blockIdx.x * 256 + threadIdx.x;
    int4 s4 = ((const int4*)src)[t];
    int4 d4 = ((const int4*)dst)[t];
    int p0 = atomicAdd(&g_cursor[d4.x], 1);
    int p1 = atomicAdd(&g_cursor[d4.y], 1);
    int p2 = atomicAdd(&g_cursor[d4.z], 1);
    int p3 = atomicAdd(&g_cursor[d4.w], 1);
    g_csrc[p0] = s4.x;
    g_csrc[p1] = s4.y;
    g_csrc[p2] = s4.z;
    g_csrc[p3] = s4.w;
}

// ---------------- AGNN edge kernel: 8 lanes per dst node ----------------
// No running max: |beta*cos| <= |beta|, subtract constant |beta| -> stable exp,
// no loop-carried rescale chain. 2-deep row pipeline + 3-deep index look-ahead.
__global__ void k_edge(const float* __restrict__ h, const float* __restrict__ betas,
                       int layer, float* __restrict__ out,
                       const float* __restrict__ invin, float* __restrict__ invout) {
    int gid = blockIdx.x * 256 + threadIdx.x;
    int n   = gid >> 3;                       // node (4 per warp)
    int sl  = threadIdx.x & 7;
    unsigned smask = 0xFFu << (threadIdx.x & 24);

    int start = g_rowptr[n];
    int deg   = g_rowptr[n + 1] - start;

    const float4* h4 = (const float4*)h;
    size_t hb = (size_t)n * 16 + sl * 2;
    float4 hd0 = h4[hb], hd1 = h4[hb + 1];

    float4 a0 = make_float4(0.f, 0.f, 0.f, 0.f);
    float4 a1 = make_float4(0.f, 0.f, 0.f, 0.f);

    if (deg > 0) {
        float beta = betas[layer];
        float bid  = beta * invin[n];
        float C    = fabsf(beta);
        float s    = 0.f;

        int i0 = g_csrc[start];
        int i1 = (deg > 1) ? g_csrc[start + 1] : i0;
        int i2 = (deg > 2) ? g_csrc[start + 2] : i1;

        size_t bA = (size_t)i0 * 16 + sl * 2;
        float4 A0 = h4[bA], A1 = h4[bA + 1];
        float  vA = invin[i0];
        size_t bB = (size_t)i1 * 16 + sl * 2;
        float4 B0 = h4[bB], B1 = h4[bB + 1];
        float  vB = invin[i1];

        for (int k = 0; k < deg; k++) {
            int i3 = (k + 3 < deg) ? g_csrc[start + k + 3] : i2;

            float4 s0 = A0, s1 = A1;
            float  invs = vA;
            A0 = B0; A1 = B1; vA = vB;
            size_t bC = (size_t)i2 * 16 + sl * 2;
            B0 = h4[bC]; B1 = h4[bC + 1]; vB = invin[i2];
            i2 = i3;

            float p = s0.x * hd0.x + s0.y * hd0.y + s0.z * hd0.z + s0.w * hd0.w
                    + s1.x * hd1.x + s1.y * hd1.y + s1.z * hd1.z + s1.w * hd1.w;
            p += __shfl_xor_sync(smask, p, 4);
            p += __shfl_xor_sync(smask, p, 2);
            p += __shfl_xor_sync(smask, p, 1);

            float ex = __expf(fmaf(bid * invs, p, -C));
            s += ex;
            a0.x += ex * s0.x;
            a0.y += ex * s0.y;
            a0.z += ex * s0.z;
            a0.w += ex * s0.w;
            a1.x += ex * s1.x;
            a1.y += ex * s1.y;
            a1.z += ex * s1.z;
            a1.w += ex * s1.w;
        }
        float rs = 1.0f / s;
        a0.x *= rs; a0.y *= rs; a0.z *= rs; a0.w *= rs;
        a1.x *= rs; a1.y *= rs; a1.z *= rs; a1.w *= rs;
    }

    ((float4*)out)[hb]     = a0;
    ((float4*)out)[hb + 1] = a1;

    if (invout) {   // fused inv-norm of the produced row (feeds next layer)
        float q = a0.x * a0.x + a0.y * a0.y + a0.z * a0.z + a0.w * a0.w
                + a1.x * a1.x + a1.y * a1.y + a1.z * a1.z + a1.w * a1.w;
        q += __shfl_xor_sync(0xffffffffu, q, 4);
        q += __shfl_xor_sync(0xffffffffu, q, 2);
        q += __shfl_xor_sync(0xffffffffu, q, 1);
        if (sl == 0) invout[n] = 1.0f / fmaxf(sqrtf(q), 1e-12f);
    }
}

// ---------------- launch ----------------
extern "C" void kernel_launch(void* const* d_in, const int* in_sizes, int n_in,
                              void* d_out, int out_size) {
    const float* features = (const float*)d_in[0];
    const int*   src      = (const int*)  d_in[1];
    const int*   dst      = (const int*)  d_in[2];
    const float* W1       = (const float*)d_in[3];
    const float* b1       = (const float*)d_in[4];
    const float* W2       = (const float*)d_in[5];
    const float* b2       = (const float*)d_in[6];
    const float* betas    = (const float*)d_in[7];
    float* out = (float*)d_out;

    float *h = nullptr, *h2 = nullptr, *invA = nullptr, *invB = nullptr;
    cudaGetSymbolAddress((void**)&h,    g_h);
    cudaGetSymbolAddress((void**)&h2,   g_h2);
    cudaGetSymbolAddress((void**)&invA, g_invA);
    cudaGetSymbolAddress((void**)&invB, g_invB);

    // 1) projection h = relu(features @ W1 + b1); also zeros g_deg
    k_gemm<IN_FEATS, true><<<N_NODES / 128, 256>>>(features, W1, b1, h, 1);

    // 2) edge histogram (4/thread) + inv-norms of h
    k_hist_norm<<<N_EDGES / 1024, 256>>>(dst, h);

    // 3) exclusive scan -> rowptr, cursor
    k_scan<<<1, 1024>>>();

    // 4) CSR scatter (4/thread)
    k_scatter<<<N_EDGES / 1024, 256>>>(src, dst);

    // 5) AGNN layer 0: h -> h2 (also writes invB for layer 1)
    k_edge<<<N_NODES * 8 / 256, 256>>>(h, betas, 0, h2, invA, invB);

    // 6) AGNN layer 1: h2 -> h
    k_edge<<<N_NODES * 8 / 256, 256>>>(h2, betas, 1, h, invB, nullptr);

    // 7) classifier: out = h @ W2 + b2
    k_gemm<N_HIDDEN, false><<<N_NODES / 128, 256>>>(h, W2, b2, out, 0);
}